// round 3
// baseline (speedup 1.0000x reference)
#include <cuda_runtime.h>
#include <math.h>

// Problem constants (fixed by reference setup_inputs)
#define BB 8192
#define DD 1024
#define NTILE 64            // 8192 / 128
#define TEMP 10.0f

// Scratch (allocation-free rule: __device__ globals)
__device__ float g_img[BB * DD];                 // normalized image embeddings
__device__ float g_txt[BB * DD];                 // normalized text embeddings
__device__ float g_partial[NTILE * NTILE];       // per-CTA loss partials

// ---------------------------------------------------------------------------
// packed f32x2 helpers (FFMA2 — only reachable via explicit PTX on sm_103a)
// ---------------------------------------------------------------------------
__device__ __forceinline__ unsigned long long pack2(float lo, float hi) {
    unsigned long long r;
    asm("mov.b64 %0, {%1, %2};" : "=l"(r) : "f"(lo), "f"(hi));
    return r;
}
__device__ __forceinline__ void ffma2(unsigned long long& d,
                                      unsigned long long a,
                                      unsigned long long b) {
    asm("fma.rn.f32x2 %0, %1, %2, %3;" : "=l"(d) : "l"(a), "l"(b), "l"(d));
}
__device__ __forceinline__ float2 unpack2(unsigned long long v) {
    float2 f;
    asm("mov.b64 {%0, %1}, %2;" : "=f"(f.x), "=f"(f.y) : "l"(v));
    return f;
}

// ---------------------------------------------------------------------------
// Kernel 1: L2-normalize rows. blocks [0,BB) -> image, [BB,2BB) -> text.
// One block per row, 256 threads, 1 float4 per thread (DD = 256*4).
// ---------------------------------------------------------------------------
__global__ __launch_bounds__(256) void normalize_k(const float* __restrict__ text,
                                                   const float* __restrict__ image) {
    int row = blockIdx.x;
    const float* src;
    float* dst;
    if (row < BB) {
        src = image + (size_t)row * DD;
        dst = g_img + (size_t)row * DD;
    } else {
        int r = row - BB;
        src = text + (size_t)r * DD;
        dst = g_txt + (size_t)r * DD;
    }
    int t = threadIdx.x;
    float4 v = ((const float4*)src)[t];
    float ss = v.x * v.x + v.y * v.y + v.z * v.z + v.w * v.w;
    #pragma unroll
    for (int o = 16; o > 0; o >>= 1) ss += __shfl_xor_sync(0xffffffffu, ss, o);

    __shared__ float ws[8];
    int warp = t >> 5, lane = t & 31;
    if (lane == 0) ws[warp] = ss;
    __syncthreads();
    if (warp == 0) {
        float s2 = (lane < 8) ? ws[lane] : 0.f;
        #pragma unroll
        for (int o = 4; o > 0; o >>= 1) s2 += __shfl_xor_sync(0xffffffffu, s2, o);
        if (lane == 0) ws[0] = s2;
    }
    __syncthreads();
    float norm = sqrtf(ws[0]);
    float s = 1.0f / fmaxf(norm, 1e-12f);   // matches torch F.normalize eps
    v.x *= s; v.y *= s; v.z *= s; v.w *= s;
    ((float4*)dst)[t] = v;
}

// ---------------------------------------------------------------------------
// Kernel 2: fused sim GEMM + sigmoid loss.
// CTA tile 128x128, BK=8, 256 threads, 8x8 per-thread tile with f32x2 accums.
// sim[i,j] = <img_i, txt_j>;  y = label(i,j) * (bias - TEMP*sim);
// partial += softplus(y) summed over the tile.
// ---------------------------------------------------------------------------
__global__ __launch_bounds__(256, 2) void gemm_loss_k(const float* __restrict__ bias) {
    __shared__ float As[8][132];   // [k][m], row stride 132*4=528 B (16B multiple)
    __shared__ float Bs[8][132];   // [k][n]

    const int bx = blockIdx.x;     // j tile
    const int by = blockIdx.y;     // i tile
    const int tid = threadIdx.x;
    const int tm = tid >> 4;       // 0..15  (8 rows each)
    const int tn = tid & 15;       // 0..15  (8 cols each)

    // acc2[i][jp] holds sim(i, 2*jp) , sim(i, 2*jp+1)
    unsigned long long acc2[8][4];
    #pragma unroll
    for (int i = 0; i < 8; i++)
        #pragma unroll
        for (int j = 0; j < 4; j++) acc2[i][j] = 0ull;

    const int lr = tid >> 1;             // 0..127: row within the 128-wide tile
    const int lk = (tid & 1) * 4;        // 0 or 4: k sub-chunk
    const float* aptr = g_img + ((size_t)(by * 128 + lr)) * DD + lk;
    const float* bptr = g_txt + ((size_t)(bx * 128 + lr)) * DD + lk;

    for (int kt = 0; kt < DD; kt += 8) {
        float4 av = *(const float4*)(aptr + kt);
        float4 bv = *(const float4*)(bptr + kt);
        __syncthreads();  // previous iteration's smem reads complete
        As[lk + 0][lr] = av.x; As[lk + 1][lr] = av.y;
        As[lk + 2][lr] = av.z; As[lk + 3][lr] = av.w;
        Bs[lk + 0][lr] = bv.x; Bs[lk + 1][lr] = bv.y;
        Bs[lk + 2][lr] = bv.z; Bs[lk + 3][lr] = bv.w;
        __syncthreads();

        #pragma unroll
        for (int k = 0; k < 8; k++) {
            float4 a0 = *(const float4*)&As[k][tm * 8];
            float4 a1 = *(const float4*)&As[k][tm * 8 + 4];
            float4 b0 = *(const float4*)&Bs[k][tn * 8];
            float4 b1 = *(const float4*)&Bs[k][tn * 8 + 4];

            unsigned long long bp[4];
            bp[0] = pack2(b0.x, b0.y);
            bp[1] = pack2(b0.z, b0.w);
            bp[2] = pack2(b1.x, b1.y);
            bp[3] = pack2(b1.z, b1.w);
            float a[8] = {a0.x, a0.y, a0.z, a0.w, a1.x, a1.y, a1.z, a1.w};

            #pragma unroll
            for (int i = 0; i < 8; i++) {
                unsigned long long ap = pack2(a[i], a[i]);
                #pragma unroll
                for (int j = 0; j < 4; j++) ffma2(acc2[i][j], ap, bp[j]);
            }
        }
    }

    // ---- fused loss epilogue ----
    const float b0 = bias[0];
    const int gi0 = by * 128 + tm * 8;
    const int gj0 = bx * 128 + tn * 8;
    float local = 0.f;
    #pragma unroll
    for (int i = 0; i < 8; i++) {
        #pragma unroll
        for (int jp = 0; jp < 4; jp++) {
            float2 sv = unpack2(acc2[i][jp]);
            #pragma unroll
            for (int h = 0; h < 2; h++) {
                float sim = (h == 0) ? sv.x : sv.y;
                int gj = gj0 + jp * 2 + h;
                float logit = fmaf(sim, -TEMP, b0);
                float y = (gi0 + i == gj) ? logit : -logit;
                // softplus(y) = max(y,0) + log1p(exp(-|y|))
                local += fmaxf(y, 0.f) + log1pf(__expf(-fabsf(y)));
            }
        }
    }

    // block reduce -> one partial per CTA (no atomics: deterministic)
    #pragma unroll
    for (int o = 16; o > 0; o >>= 1) local += __shfl_xor_sync(0xffffffffu, local, o);
    __shared__ float red[8];
    if ((tid & 31) == 0) red[tid >> 5] = local;
    __syncthreads();
    if (tid < 8) {
        float s = red[tid];
        #pragma unroll
        for (int o = 4; o > 0; o >>= 1) s += __shfl_xor_sync(0x000000ffu, s, o);
        if (tid == 0) g_partial[by * NTILE + bx] = s;
    }
}

// ---------------------------------------------------------------------------
// Kernel 3: reduce 4096 partials, divide by B, write scalar.
// ---------------------------------------------------------------------------
__global__ __launch_bounds__(256) void final_reduce_k(float* __restrict__ out) {
    int t = threadIdx.x;
    float s = 0.f;
    for (int i = t; i < NTILE * NTILE; i += 256) s += g_partial[i];
    #pragma unroll
    for (int o = 16; o > 0; o >>= 1) s += __shfl_xor_sync(0xffffffffu, s, o);
    __shared__ float ws[8];
    if ((t & 31) == 0) ws[t >> 5] = s;
    __syncthreads();
    if (t == 0) {
        float tot = 0.f;
        #pragma unroll
        for (int i = 0; i < 8; i++) tot += ws[i];
        out[0] = tot / (float)BB;   // reference: sum(softplus(labels*logits)) / B
    }
}

// ---------------------------------------------------------------------------
extern "C" void kernel_launch(void* const* d_in, const int* in_sizes, int n_in,
                              void* d_out, int out_size) {
    const float* text  = (const float*)d_in[0];
    const float* image = (const float*)d_in[1];
    const float* bias  = (const float*)d_in[2];

    normalize_k<<<2 * BB, 256>>>(text, image);
    dim3 grid(NTILE, NTILE);
    gemm_loss_k<<<grid, 256>>>(bias);
    final_reduce_k<<<1, 256>>>((float*)d_out);
}

// round 5
// speedup vs baseline: 5.6378x; 5.6378x over previous
#include <cuda_runtime.h>
#include <cuda_bf16.h>
#include <stdint.h>
#include <math.h>

// Problem constants (fixed by reference setup_inputs)
#define BB 8192
#define DD 1024
#define TEMP 10.0f

// GEMM tiling
#define BM 128
#define BN 128
#define BK 32
#define STAGES 3
#define STRIDE_B2 40            // bf16 elements per smem row (80 B) -> conflict-free ldmatrix
#define STAGE_BYTES (2 * BM * STRIDE_B2 * 2)   // A(10240) + B(10240) = 20480
#define NTX 64                  // 8192 / BN
#define NTY 64                  // 8192 / BM

// Scratch (allocation-free rule: __device__ globals)
__device__ __nv_bfloat16 g_imgh[BB * DD];
__device__ __nv_bfloat16 g_txth[BB * DD];
__device__ float g_partial[NTX * NTY];

// ---------------------------------------------------------------------------
// helpers
// ---------------------------------------------------------------------------
__device__ __forceinline__ uint32_t smem_u32(const void* p) {
    uint32_t a;
    asm("{ .reg .u64 t; cvta.to.shared.u64 t, %1; cvt.u32.u64 %0, t; }" : "=r"(a) : "l"(p));
    return a;
}
__device__ __forceinline__ void cp_async16(uint32_t dst, const void* src) {
    asm volatile("cp.async.cg.shared.global [%0], [%1], 16;" :: "r"(dst), "l"(src));
}
__device__ __forceinline__ void cp_commit() {
    asm volatile("cp.async.commit_group;" ::: "memory");
}
__device__ __forceinline__ void cp_wait1() {
    asm volatile("cp.async.wait_group 1;" ::: "memory");
}
__device__ __forceinline__ void ldsm_x4(uint32_t* r, uint32_t addr) {
    asm volatile("ldmatrix.sync.aligned.m8n8.x4.shared.b16 {%0,%1,%2,%3}, [%4];"
                 : "=r"(r[0]), "=r"(r[1]), "=r"(r[2]), "=r"(r[3]) : "r"(addr));
}
__device__ __forceinline__ void mma_bf16(float* c, const uint32_t* a, const uint32_t* b) {
    asm volatile(
        "mma.sync.aligned.m16n8k16.row.col.f32.bf16.bf16.f32 "
        "{%0,%1,%2,%3}, {%4,%5,%6,%7}, {%8,%9}, {%0,%1,%2,%3};"
        : "+f"(c[0]), "+f"(c[1]), "+f"(c[2]), "+f"(c[3])
        : "r"(a[0]), "r"(a[1]), "r"(a[2]), "r"(a[3]), "r"(b[0]), "r"(b[1]));
}

// ---------------------------------------------------------------------------
// Kernel 1: L2-normalize rows, emit bf16. blocks [0,BB)->image, [BB,2BB)->text
// ---------------------------------------------------------------------------
__global__ __launch_bounds__(256) void normalize_bf16_k(const float* __restrict__ text,
                                                        const float* __restrict__ image) {
    int row = blockIdx.x;
    const float* src;
    __nv_bfloat16* dst;
    if (row < BB) {
        src = image + (size_t)row * DD;
        dst = g_imgh + (size_t)row * DD;
    } else {
        int r = row - BB;
        src = text + (size_t)r * DD;
        dst = g_txth + (size_t)r * DD;
    }
    int t = threadIdx.x;
    float4 v = ((const float4*)src)[t];
    float ss = v.x * v.x + v.y * v.y + v.z * v.z + v.w * v.w;
    #pragma unroll
    for (int o = 16; o > 0; o >>= 1) ss += __shfl_xor_sync(0xffffffffu, ss, o);

    __shared__ float ws[8];
    int warp = t >> 5, lane = t & 31;
    if (lane == 0) ws[warp] = ss;
    __syncthreads();
    if (warp == 0) {
        float s2 = (lane < 8) ? ws[lane] : 0.f;
        #pragma unroll
        for (int o = 4; o > 0; o >>= 1) s2 += __shfl_xor_sync(0xffffffffu, s2, o);
        if (lane == 0) ws[0] = s2;
    }
    __syncthreads();
    float s = 1.0f / fmaxf(sqrtf(ws[0]), 1e-12f);   // torch F.normalize eps
    __nv_bfloat162 p0 = __floats2bfloat162_rn(v.x * s, v.y * s);
    __nv_bfloat162 p1 = __floats2bfloat162_rn(v.z * s, v.w * s);
    uint2 u;
    u.x = *reinterpret_cast<uint32_t*>(&p0);
    u.y = *reinterpret_cast<uint32_t*>(&p1);
    *reinterpret_cast<uint2*>(dst + t * 4) = u;
}

// ---------------------------------------------------------------------------
// Kernel 2: bf16 mma.sync GEMM (128x128 tile, 8 warps, warp tile 64x32)
// with 3-stage cp.async pipeline + fused sigmoid loss epilogue.
// ---------------------------------------------------------------------------
__global__ __launch_bounds__(256) void gemm_loss_mma(const float* __restrict__ bias) {
    extern __shared__ char smem[];
    const uint32_t sbase = smem_u32(smem);
    const int tid = threadIdx.x;
    const int wid = tid >> 5;
    const int lane = tid & 31;
    const int bx = blockIdx.x;   // N tile (txt rows)
    const int by = blockIdx.y;   // M tile (img rows)

    const int wm = wid >> 2;     // 0..1  (64-row slab)
    const int wn = wid & 3;      // 0..3  (32-col slab)

    // accumulators: 4 m16-tiles x 4 n8-tiles x 4 regs
    float acc[4][4][4];
    #pragma unroll
    for (int i = 0; i < 4; i++)
        #pragma unroll
        for (int j = 0; j < 4; j++)
            #pragma unroll
            for (int k = 0; k < 4; k++) acc[i][j][k] = 0.f;

    // ---- cp.async loader mapping: 1024 x 16B chunks per stage, 4 per thread
    const __nv_bfloat16* ag = g_imgh + (size_t)(by * BM) * DD;
    const __nv_bfloat16* bg = g_txth + (size_t)(bx * BN) * DD;

    auto issue_stage = [&](int kc, int stg) {
        uint32_t abase = sbase + stg * STAGE_BYTES;
        #pragma unroll
        for (int o = 0; o < 4; o++) {
            int idx = o * 256 + tid;
            int r = (idx >> 2) & 127;
            int ch = idx & 3;
            if (idx < 512) {
                cp_async16(abase + r * 80 + ch * 16,
                           ag + (size_t)r * DD + kc * BK + ch * 8);
            } else {
                cp_async16(abase + 10240 + r * 80 + ch * 16,
                           bg + (size_t)r * DD + kc * BK + ch * 8);
            }
        }
        cp_commit();
    };

    issue_stage(0, 0);
    issue_stage(1, 1);

    // per-thread ldmatrix address components
    const int arow = lane & 15;              // A: lanes 0-15 rows, 16-31 k-hi
    const uint32_t ahi = (lane >> 4) * 16;
    const int bmi = lane >> 3;               // B: matrix index 0..3
    const int brow = lane & 7;
    const int bnoff = (bmi >> 1) * 8;        // n offset within 16-col pair
    const uint32_t bhi = (bmi & 1) * 16;     // k-half

    const int NKI = DD / BK;   // 32
    for (int kc = 0; kc < NKI; kc++) {
        cp_wait1();
        __syncthreads();
        if (kc + 2 < NKI) issue_stage(kc + 2, (kc + 2) % STAGES);
        else cp_commit();   // empty group keeps the wait_group accounting uniform

        const uint32_t abase = sbase + (kc % STAGES) * STAGE_BYTES;
        const uint32_t bbase = abase + 10240;

        #pragma unroll
        for (int ks = 0; ks < 2; ks++) {
            uint32_t afrag[4][4], bfrag[2][4];
            #pragma unroll
            for (int mt = 0; mt < 4; mt++) {
                uint32_t addr = abase + (wm * 64 + mt * 16 + arow) * 80 + ks * 32 + ahi;
                ldsm_x4(afrag[mt], addr);
            }
            #pragma unroll
            for (int p = 0; p < 2; p++) {   // n8-tile pairs (2p, 2p+1)
                uint32_t addr = bbase + (wn * 32 + p * 16 + bnoff + brow) * 80 + ks * 32 + bhi;
                ldsm_x4(bfrag[p], addr);
            }
            #pragma unroll
            for (int mt = 0; mt < 4; mt++)
                #pragma unroll
                for (int nt = 0; nt < 4; nt++)
                    mma_bf16(acc[mt][nt], afrag[mt], &bfrag[nt >> 1][(nt & 1) * 2]);
        }
        __syncthreads();
    }

    // ---- fused loss epilogue (fragment layout: c0:(r,c) c1:(r,c+1) c2:(r+8,c) c3:(r+8,c+1))
    const float b0v = bias[0];
    const int gr = lane >> 2;        // group row 0..7
    const int gc = (lane & 3) * 2;   // group col
    float local = 0.f;
    #pragma unroll
    for (int mt = 0; mt < 4; mt++) {
        const int m0 = by * BM + wm * 64 + mt * 16 + gr;
        #pragma unroll
        for (int nt = 0; nt < 4; nt++) {
            const int n0 = bx * BN + wn * 32 + nt * 8 + gc;
            #pragma unroll
            for (int k = 0; k < 4; k++) {
                int m = m0 + (k >> 1) * 8;
                int n = n0 + (k & 1);
                float logit = fmaf(acc[mt][nt][k], -TEMP, b0v);
                float y = (m == n) ? logit : -logit;
                local += fmaxf(y, 0.f) + log1pf(__expf(-fabsf(y)));
            }
        }
    }

    // block reduce -> one partial per CTA (deterministic, no atomics)
    #pragma unroll
    for (int o = 16; o > 0; o >>= 1) local += __shfl_xor_sync(0xffffffffu, local, o);
    __shared__ float red[8];
    if (lane == 0) red[wid] = local;
    __syncthreads();
    if (tid == 0) {
        float s = 0.f;
        #pragma unroll
        for (int i = 0; i < 8; i++) s += red[i];
        g_partial[by * NTX + bx] = s;
    }
}

// ---------------------------------------------------------------------------
// Kernel 3: reduce NTX*NTY partials -> scalar
// ---------------------------------------------------------------------------
__global__ __launch_bounds__(256) void final_reduce_k(float* __restrict__ out) {
    int t = threadIdx.x;
    float s = 0.f;
    for (int i = t; i < NTX * NTY; i += 256) s += g_partial[i];
    #pragma unroll
    for (int o = 16; o > 0; o >>= 1) s += __shfl_xor_sync(0xffffffffu, s, o);
    __shared__ float ws[8];
    if ((t & 31) == 0) ws[t >> 5] = s;
    __syncthreads();
    if (t == 0) {
        float tot = 0.f;
        #pragma unroll
        for (int i = 0; i < 8; i++) tot += ws[i];
        out[0] = tot / (float)BB;
    }
}

// ---------------------------------------------------------------------------
extern "C" void kernel_launch(void* const* d_in, const int* in_sizes, int n_in,
                              void* d_out, int out_size) {
    const float* text  = (const float*)d_in[0];
    const float* image = (const float*)d_in[1];
    const float* bias  = (const float*)d_in[2];

    const int smem_bytes = STAGES * STAGE_BYTES;   // 61440
    cudaFuncSetAttribute(gemm_loss_mma, cudaFuncAttributeMaxDynamicSharedMemorySize, smem_bytes);

    normalize_bf16_k<<<2 * BB, 256>>>(text, image);
    gemm_loss_mma<<<dim3(NTX, NTY), 256, smem_bytes>>>(bias);
    final_reduce_k<<<1, 256>>>((float*)d_out);
}

// round 6
// speedup vs baseline: 7.9215x; 1.4051x over previous
#include <cuda_runtime.h>
#include <cuda_fp16.h>
#include <stdint.h>
#include <math.h>

// Problem constants (fixed by reference setup_inputs)
#define BB 8192
#define DD 1024
#define TEMP 10.0f

// GEMM tiling: CTA 128x128, 4 warps (2x2), warp tile 64x64, BK=32, 3 stages
#define BM 128
#define BN 128
#define BK 32
#define STAGES 3
#define ROWB 80                 // bytes per smem row (32 fp16 = 64B + 16B pad)
#define STAGE_BYTES (2 * BM * ROWB)   // A(10240) + B(10240) = 20480
#define NTX 64
#define NTY 64

// Scratch (allocation-free rule: __device__ globals)
__device__ __half g_imgh[BB * DD];
__device__ __half g_txth[BB * DD];
__device__ float g_partial[NTX * NTY];

// ---------------------------------------------------------------------------
// helpers
// ---------------------------------------------------------------------------
__device__ __forceinline__ uint32_t smem_u32(const void* p) {
    uint32_t a;
    asm("{ .reg .u64 t; cvta.to.shared.u64 t, %1; cvt.u32.u64 %0, t; }" : "=r"(a) : "l"(p));
    return a;
}
__device__ __forceinline__ void cp_async16(uint32_t dst, const void* src) {
    asm volatile("cp.async.cg.shared.global [%0], [%1], 16;" :: "r"(dst), "l"(src));
}
__device__ __forceinline__ void cp_commit() {
    asm volatile("cp.async.commit_group;" ::: "memory");
}
__device__ __forceinline__ void cp_wait1() {
    asm volatile("cp.async.wait_group 1;" ::: "memory");
}
__device__ __forceinline__ void ldsm_x4(uint32_t* r, uint32_t addr) {
    asm volatile("ldmatrix.sync.aligned.m8n8.x4.shared.b16 {%0,%1,%2,%3}, [%4];"
                 : "=r"(r[0]), "=r"(r[1]), "=r"(r[2]), "=r"(r[3]) : "r"(addr));
}
// fp16 in, fp16 accumulate (packed half2 x2)
__device__ __forceinline__ void mma_f16(uint32_t* c, const uint32_t* a, const uint32_t* b) {
    asm volatile(
        "mma.sync.aligned.m16n8k16.row.col.f16.f16.f16.f16 "
        "{%0,%1}, {%2,%3,%4,%5}, {%6,%7}, {%0,%1};"
        : "+r"(c[0]), "+r"(c[1])
        : "r"(a[0]), "r"(a[1]), "r"(a[2]), "r"(a[3]), "r"(b[0]), "r"(b[1]));
}

// ---------------------------------------------------------------------------
// Kernel 1: L2-normalize rows, emit fp16. blocks [0,BB)->image, [BB,2BB)->text
// ---------------------------------------------------------------------------
__global__ __launch_bounds__(256) void normalize_f16_k(const float* __restrict__ text,
                                                       const float* __restrict__ image) {
    int row = blockIdx.x;
    const float* src;
    __half* dst;
    if (row < BB) {
        src = image + (size_t)row * DD;
        dst = g_imgh + (size_t)row * DD;
    } else {
        int r = row - BB;
        src = text + (size_t)r * DD;
        dst = g_txth + (size_t)r * DD;
    }
    int t = threadIdx.x;
    float4 v = ((const float4*)src)[t];
    float ss = v.x * v.x + v.y * v.y + v.z * v.z + v.w * v.w;
    #pragma unroll
    for (int o = 16; o > 0; o >>= 1) ss += __shfl_xor_sync(0xffffffffu, ss, o);

    __shared__ float ws[8];
    int warp = t >> 5, lane = t & 31;
    if (lane == 0) ws[warp] = ss;
    __syncthreads();
    if (warp == 0) {
        float s2 = (lane < 8) ? ws[lane] : 0.f;
        #pragma unroll
        for (int o = 4; o > 0; o >>= 1) s2 += __shfl_xor_sync(0xffffffffu, s2, o);
        if (lane == 0) ws[0] = s2;
    }
    __syncthreads();
    float s = 1.0f / fmaxf(sqrtf(ws[0]), 1e-12f);   // torch F.normalize eps
    __half2 p0 = __floats2half2_rn(v.x * s, v.y * s);
    __half2 p1 = __floats2half2_rn(v.z * s, v.w * s);
    uint2 u;
    u.x = *reinterpret_cast<uint32_t*>(&p0);
    u.y = *reinterpret_cast<uint32_t*>(&p1);
    *reinterpret_cast<uint2*>(dst + t * 4) = u;
}

// ---------------------------------------------------------------------------
// Kernel 2: fp16 mma.sync GEMM (128x128 CTA tile, 4 warps, warp tile 64x64,
// fp16 accumulators) + fused sigmoid loss epilogue.
// ---------------------------------------------------------------------------
__global__ __launch_bounds__(128, 3) void gemm_loss_mma(const float* __restrict__ bias) {
    extern __shared__ char smem[];
    const uint32_t sbase = smem_u32(smem);
    const int tid = threadIdx.x;
    const int wid = tid >> 5;
    const int lane = tid & 31;
    const int bx = blockIdx.x;   // N tile (txt rows)
    const int by = blockIdx.y;   // M tile (img rows)

    const int wm = wid >> 1;     // 0..1 (64-row slab)
    const int wn = wid & 1;      // 0..1 (64-col slab)

    // accumulators: 4 m16 x 8 n8 x 2 packed-half2 regs
    uint32_t acc[4][8][2];
    #pragma unroll
    for (int i = 0; i < 4; i++)
        #pragma unroll
        for (int j = 0; j < 8; j++) { acc[i][j][0] = 0u; acc[i][j][1] = 0u; }

    const __half* ag = g_imgh + (size_t)(by * BM) * DD;
    const __half* bg = g_txth + (size_t)(bx * BN) * DD;

    // loader: 1024 x 16B chunks per stage, 8 per thread
    auto issue_stage = [&](int kc, int stg) {
        uint32_t abase = sbase + stg * STAGE_BYTES;
        #pragma unroll
        for (int o = 0; o < 8; o++) {
            int idx = o * 128 + tid;
            int r = (idx >> 2) & 127;
            int ch = idx & 3;
            if (idx < 512) {
                cp_async16(abase + r * ROWB + ch * 16,
                           ag + (size_t)r * DD + kc * BK + ch * 8);
            } else {
                cp_async16(abase + 10240 + r * ROWB + ch * 16,
                           bg + (size_t)r * DD + kc * BK + ch * 8);
            }
        }
        cp_commit();
    };

    issue_stage(0, 0);
    issue_stage(1, 1);

    // ldmatrix address components
    const int arow = lane & 15;
    const uint32_t ahi = (lane >> 4) * 16;
    const int bmi = lane >> 3;
    const int brow = lane & 7;
    const int bnoff = (bmi >> 1) * 8;
    const uint32_t bhi = (bmi & 1) * 16;

    const int NKI = DD / BK;   // 32
    for (int kc = 0; kc < NKI; kc++) {
        cp_wait1();
        __syncthreads();
        if (kc + 2 < NKI) issue_stage(kc + 2, (kc + 2) % STAGES);
        else cp_commit();   // keep wait_group accounting uniform

        const uint32_t abase = sbase + (kc % STAGES) * STAGE_BYTES;
        const uint32_t bbase = abase + 10240;

        #pragma unroll
        for (int ks = 0; ks < 2; ks++) {
            uint32_t afrag[4][4], bfrag[4][4];
            #pragma unroll
            for (int mt = 0; mt < 4; mt++)
                ldsm_x4(afrag[mt], abase + (wm * 64 + mt * 16 + arow) * ROWB + ks * 32 + ahi);
            #pragma unroll
            for (int p = 0; p < 4; p++)   // n8 pairs (2p, 2p+1)
                ldsm_x4(bfrag[p], bbase + (wn * 64 + p * 16 + bnoff + brow) * ROWB + ks * 32 + bhi);

            #pragma unroll
            for (int mt = 0; mt < 4; mt++)
                #pragma unroll
                for (int nt = 0; nt < 8; nt++)
                    mma_f16(acc[mt][nt], afrag[mt], &bfrag[nt >> 1][(nt & 1) * 2]);
        }
        __syncthreads();
    }

    // ---- fused loss epilogue ----
    // f16 acc layout: reg0 = half2{(gr,gc),(gr,gc+1)}, reg1 = same at gr+8
    const float b0v = bias[0];
    const int gr = lane >> 2;
    const int gc = (lane & 3) * 2;
    float local = 0.f;
    #pragma unroll
    for (int mt = 0; mt < 4; mt++) {
        const int m0 = by * BM + wm * 64 + mt * 16 + gr;
        #pragma unroll
        for (int nt = 0; nt < 8; nt++) {
            const int n0 = bx * BN + wn * 64 + nt * 8 + gc;
            #pragma unroll
            for (int k = 0; k < 2; k++) {
                __half2 h = *reinterpret_cast<__half2*>(&acc[mt][nt][k]);
                float2 sv = __half22float2(h);
                int m = m0 + k * 8;
                #pragma unroll
                for (int e = 0; e < 2; e++) {
                    float sim = (e == 0) ? sv.x : sv.y;
                    float logit = fmaf(sim, -TEMP, b0v);
                    float y = (m == n0 + e) ? logit : -logit;
                    local += fmaxf(y, 0.f) + __logf(1.f + __expf(-fabsf(y)));
                }
            }
        }
    }

    // block reduce -> one partial per CTA (deterministic, no atomics)
    #pragma unroll
    for (int o = 16; o > 0; o >>= 1) local += __shfl_xor_sync(0xffffffffu, local, o);
    __shared__ float red[4];
    if (lane == 0) red[wid] = local;
    __syncthreads();
    if (tid == 0) {
        g_partial[by * NTX + bx] = red[0] + red[1] + red[2] + red[3];
    }
}

// ---------------------------------------------------------------------------
// Kernel 3: reduce NTX*NTY partials -> scalar
// ---------------------------------------------------------------------------
__global__ __launch_bounds__(256) void final_reduce_k(float* __restrict__ out) {
    int t = threadIdx.x;
    float s = 0.f;
    for (int i = t; i < NTX * NTY; i += 256) s += g_partial[i];
    #pragma unroll
    for (int o = 16; o > 0; o >>= 1) s += __shfl_xor_sync(0xffffffffu, s, o);
    __shared__ float ws[8];
    if ((t & 31) == 0) ws[t >> 5] = s;
    __syncthreads();
    if (t == 0) {
        float tot = 0.f;
        #pragma unroll
        for (int i = 0; i < 8; i++) tot += ws[i];
        out[0] = tot / (float)BB;
    }
}

// ---------------------------------------------------------------------------
extern "C" void kernel_launch(void* const* d_in, const int* in_sizes, int n_in,
                              void* d_out, int out_size) {
    const float* text  = (const float*)d_in[0];
    const float* image = (const float*)d_in[1];
    const float* bias  = (const float*)d_in[2];

    const int smem_bytes = STAGES * STAGE_BYTES;   // 61440
    cudaFuncSetAttribute(gemm_loss_mma, cudaFuncAttributeMaxDynamicSharedMemorySize, smem_bytes);

    normalize_f16_k<<<2 * BB, 256>>>(text, image);
    gemm_loss_mma<<<dim3(NTX, NTY), 128, smem_bytes>>>(bias);
    final_reduce_k<<<1, 256>>>((float*)d_out);
}